// round 1
// baseline (speedup 1.0000x reference)
#include <cuda_runtime.h>
#include <math.h>

// Problem dims (fixed by setup_inputs)
#define T_TOK 8192      // B*S tokens
#define D_DIM 2048
#define E_EXP 8
#define H_DIM 2048
#define C_CAP 2048      // capacity = k*T/E
#define B_BATCH 4
#define S_SEQ 2048

// ---------------- device scratch (allocation-free) ----------------
__device__ int   g_e0[T_TOK], g_e1[T_TOK];
__device__ float g_g0[T_TOK], g_g1[T_TOK];
__device__ int   g_p0[T_TOK], g_p1[T_TOK];      // position in expert buffer, -1 if dropped
__device__ int   g_src[E_EXP * C_CAP];          // token id filling slot (e,c), -1 empty
__device__ float g_w2sum[E_EXP * H_DIM];        // sum_d W2[e,h,d]
__device__ float g_b2sum[E_EXP];                // sum_d b2[e,d]
__device__ float g_rowsum[E_EXP * C_CAP];       // sum_h relu(z)*w2sum
__device__ float g_y[T_TOK];

// ---------------- K0: per-launch reset (graph replays must be deterministic) ----------------
__global__ void k_init() {
    int i = blockIdx.x * blockDim.x + threadIdx.x;
    if (i < E_EXP * C_CAP) {
        g_src[i] = -1;
        g_rowsum[i] = 0.f;
    }
}

// ---------------- K1: gating (logits + top2 + normalized gates) ----------------
// one warp per token; 8 warps / block
__global__ void k_gate(const float* __restrict__ x, const float* __restrict__ Wg) {
    int warp = threadIdx.x >> 5;
    int lane = threadIdx.x & 31;
    int tok = blockIdx.x * 8 + warp;
    if (tok >= T_TOK) return;
    const float* xr = x + (size_t)tok * D_DIM;

    float acc[8];
#pragma unroll
    for (int e = 0; e < 8; e++) acc[e] = 0.f;

    for (int k = lane; k < D_DIM; k += 32) {
        float xv = xr[k];
        const float* wr = Wg + (size_t)k * 8;
        float4 w0 = *(const float4*)(wr);
        float4 w1 = *(const float4*)(wr + 4);
        acc[0] = fmaf(xv, w0.x, acc[0]);
        acc[1] = fmaf(xv, w0.y, acc[1]);
        acc[2] = fmaf(xv, w0.z, acc[2]);
        acc[3] = fmaf(xv, w0.w, acc[3]);
        acc[4] = fmaf(xv, w1.x, acc[4]);
        acc[5] = fmaf(xv, w1.y, acc[5]);
        acc[6] = fmaf(xv, w1.z, acc[6]);
        acc[7] = fmaf(xv, w1.w, acc[7]);
    }
#pragma unroll
    for (int e = 0; e < 8; e++) {
#pragma unroll
        for (int off = 16; off > 0; off >>= 1)
            acc[e] += __shfl_xor_sync(0xffffffffu, acc[e], off);
    }
    if (lane == 0) {
        // top-1: strict > keeps lowest index on ties (matches lax.top_k)
        float l0 = acc[0]; int i0 = 0;
#pragma unroll
        for (int e = 1; e < 8; e++) if (acc[e] > l0) { l0 = acc[e]; i0 = e; }
        float l1 = -INFINITY; int i1 = 0;
#pragma unroll
        for (int e = 0; e < 8; e++) if (e != i0 && acc[e] > l1) { l1 = acc[e]; i1 = e; }
        // normalized top-2 gates = 2-way softmax of top-2 logits
        float g0 = 1.f / (1.f + __expf(l1 - l0));  // l1 <= l0, stable
        g_e0[tok] = i0; g_e1[tok] = i1;
        g_g0[tok] = g0; g_g1[tok] = 1.f - g0;
    }
}

// ---------------- K2: dispatch scan (single block) ----------------
// Order: all choice-0 assignments in token order, then all choice-1 (GShard k-major).
#define SCAN_T 512
#define TOK_PER_T (T_TOK / SCAN_T)   // 16
__global__ void k_scan() {
    __shared__ int shCnt[SCAN_T * 8];
    __shared__ int shScan[SCAN_T * 8];
    __shared__ int shTot[8];
    int t = threadIdx.x;

    // -------- choice 0 --------
    for (int e = 0; e < 8; e++) shCnt[t * 8 + e] = 0;
    for (int i = 0; i < TOK_PER_T; i++) {
        int tok = t * TOK_PER_T + i;
        shCnt[t * 8 + g_e0[tok]]++;
    }
    for (int e = 0; e < 8; e++) shScan[t * 8 + e] = shCnt[t * 8 + e];
    __syncthreads();
    // inclusive Hillis-Steele scan over 512 rows of int8-vectors
    for (int s = 1; s < SCAN_T; s <<= 1) {
        int v[8];
        if (t >= s) {
            for (int e = 0; e < 8; e++) v[e] = shScan[(t - s) * 8 + e];
        }
        __syncthreads();
        if (t >= s) {
            for (int e = 0; e < 8; e++) shScan[t * 8 + e] += v[e];
        }
        __syncthreads();
    }
    if (t == 0) {
        for (int e = 0; e < 8; e++) shTot[e] = shScan[(SCAN_T - 1) * 8 + e];
    }
    // exclusive offset -> running counter in shCnt
    for (int e = 0; e < 8; e++) shCnt[t * 8 + e] = shScan[t * 8 + e] - shCnt[t * 8 + e];
    __syncthreads();
    for (int i = 0; i < TOK_PER_T; i++) {
        int tok = t * TOK_PER_T + i;
        int e = g_e0[tok];
        int pos = shCnt[t * 8 + e]++;   // count ALL prior assignments (incl. overflow)
        if (pos < C_CAP) { g_p0[tok] = pos; g_src[e * C_CAP + pos] = tok; }
        else             { g_p0[tok] = -1; }
    }
    __syncthreads();

    // -------- choice 1 (base = total choice-0 counts) --------
    for (int e = 0; e < 8; e++) shCnt[t * 8 + e] = 0;
    for (int i = 0; i < TOK_PER_T; i++) {
        int tok = t * TOK_PER_T + i;
        shCnt[t * 8 + g_e1[tok]]++;
    }
    for (int e = 0; e < 8; e++) shScan[t * 8 + e] = shCnt[t * 8 + e];
    __syncthreads();
    for (int s = 1; s < SCAN_T; s <<= 1) {
        int v[8];
        if (t >= s) {
            for (int e = 0; e < 8; e++) v[e] = shScan[(t - s) * 8 + e];
        }
        __syncthreads();
        if (t >= s) {
            for (int e = 0; e < 8; e++) shScan[t * 8 + e] += v[e];
        }
        __syncthreads();
    }
    for (int e = 0; e < 8; e++)
        shCnt[t * 8 + e] = shScan[t * 8 + e] - shCnt[t * 8 + e] + shTot[e];
    __syncthreads();
    for (int i = 0; i < TOK_PER_T; i++) {
        int tok = t * TOK_PER_T + i;
        int e = g_e1[tok];
        int pos = shCnt[t * 8 + e]++;
        if (pos < C_CAP) { g_p1[tok] = pos; g_src[e * C_CAP + pos] = tok; }
        else             { g_p1[tok] = -1; }
    }
}

// ---------------- K3a: w2sum[e,h] = sum_d W2[e,h,d] ----------------
__global__ void k_w2sum(const float* __restrict__ W2) {
    int gw = (blockIdx.x * blockDim.x + threadIdx.x) >> 5;
    int lane = threadIdx.x & 31;
    if (gw >= E_EXP * H_DIM) return;
    const float* r = W2 + (size_t)gw * D_DIM;
    float s = 0.f;
    for (int k = lane * 4; k < D_DIM; k += 128) {
        float4 v = *(const float4*)(r + k);
        s += (v.x + v.y) + (v.z + v.w);
    }
#pragma unroll
    for (int off = 16; off > 0; off >>= 1) s += __shfl_xor_sync(0xffffffffu, s, off);
    if (lane == 0) g_w2sum[gw] = s;
}

// ---------------- K3b: b2sum[e] = sum_d b2[e,d] ----------------
__global__ void k_b2sum(const float* __restrict__ b2) {
    int w = threadIdx.x >> 5, lane = threadIdx.x & 31;
    if (w >= E_EXP) return;
    float s = 0.f;
    for (int k = lane; k < D_DIM; k += 32) s += b2[(size_t)w * D_DIM + k];
#pragma unroll
    for (int off = 16; off > 0; off >>= 1) s += __shfl_xor_sync(0xffffffffu, s, off);
    if (lane == 0) g_b2sum[w] = s;
}

// ---------------- K4: fused expert GEMM + relu + w2sum reduction ----------------
// z[c,h] = sum_d x[src[e,c],d] * W1[e,d,h] + b1[e,h]
// rowsum[e,c] += sum_h relu(z[c,h]) * w2sum[e,h]   (atomicAdd over H tiles)
#define BM 128
#define BN 128
#define BK 8
__global__ void __launch_bounds__(256) k_ffn(const float* __restrict__ x,
                                             const float* __restrict__ W1,
                                             const float* __restrict__ b1) {
    __shared__ float As[2][BK][BM];   // transposed A tile
    __shared__ float Bs[2][BK][BN];
    __shared__ int   sSrc[BM];
    __shared__ float sW2[BN];
    __shared__ float sB1[BN];

    const int e    = blockIdx.z;
    const int row0 = blockIdx.y * BM;
    const int col0 = blockIdx.x * BN;
    const int tid  = threadIdx.x;

    if (tid < BM) sSrc[tid] = g_src[e * C_CAP + row0 + tid];
    if (tid < BN) {
        sW2[tid] = g_w2sum[(size_t)e * H_DIM + col0 + tid];
        sB1[tid] = b1[(size_t)e * H_DIM + col0 + tid];
    }
    __syncthreads();

    // loaders
    const int ar = tid >> 1;            // A row within tile 0..127
    const int ak = (tid & 1) * 4;       // A k offset 0 or 4
    const int bk = tid >> 5;            // B k row 0..7
    const int bc = (tid & 31) * 4;      // B col 0..124

    const int srcTok = sSrc[ar];
    const float* Aptr = x + (size_t)(srcTok >= 0 ? srcTok : 0) * D_DIM + ak;
    const float* Wbase = W1 + (size_t)e * D_DIM * H_DIM + col0;

    float4 aReg, bReg;
    const float4 zero4 = make_float4(0.f, 0.f, 0.f, 0.f);

    // preload tile 0
    aReg = (srcTok >= 0) ? *(const float4*)(Aptr) : zero4;
    bReg = *(const float4*)(Wbase + (size_t)bk * H_DIM + bc);
    As[0][ak + 0][ar] = aReg.x; As[0][ak + 1][ar] = aReg.y;
    As[0][ak + 2][ar] = aReg.z; As[0][ak + 3][ar] = aReg.w;
    *(float4*)&Bs[0][bk][bc] = bReg;
    __syncthreads();

    const int tx = tid & 15;   // col group: cols tx*8..+7
    const int ty = tid >> 4;   // row group: rows ty*8..+7

    float acc[8][8];
#pragma unroll
    for (int i = 0; i < 8; i++)
#pragma unroll
        for (int j = 0; j < 8; j++) acc[i][j] = 0.f;

    const int NK = D_DIM / BK;  // 256
    for (int kt = 0; kt < NK; kt++) {
        const int buf = kt & 1;
        if (kt + 1 < NK) {
            const int kbase = (kt + 1) * BK;
            aReg = (srcTok >= 0) ? *(const float4*)(Aptr + kbase) : zero4;
            bReg = *(const float4*)(Wbase + (size_t)(kbase + bk) * H_DIM + bc);
        }
#pragma unroll
        for (int kk = 0; kk < BK; kk++) {
            float a[8], b[8];
            *(float4*)(a)     = *(const float4*)&As[buf][kk][ty * 8];
            *(float4*)(a + 4) = *(const float4*)&As[buf][kk][ty * 8 + 4];
            *(float4*)(b)     = *(const float4*)&Bs[buf][kk][tx * 8];
            *(float4*)(b + 4) = *(const float4*)&Bs[buf][kk][tx * 8 + 4];
#pragma unroll
            for (int i = 0; i < 8; i++)
#pragma unroll
                for (int j = 0; j < 8; j++)
                    acc[i][j] = fmaf(a[i], b[j], acc[i][j]);
        }
        if (kt + 1 < NK) {
            const int nb = buf ^ 1;
            As[nb][ak + 0][ar] = aReg.x; As[nb][ak + 1][ar] = aReg.y;
            As[nb][ak + 2][ar] = aReg.z; As[nb][ak + 3][ar] = aReg.w;
            *(float4*)&Bs[nb][bk][bc] = bReg;
        }
        __syncthreads();
    }

    // epilogue: relu + dot with w2sum, reduce across the 16 col-group threads
    float w2f[8], b1f[8];
    *(float4*)(w2f)     = *(const float4*)&sW2[tx * 8];
    *(float4*)(w2f + 4) = *(const float4*)&sW2[tx * 8 + 4];
    *(float4*)(b1f)     = *(const float4*)&sB1[tx * 8];
    *(float4*)(b1f + 4) = *(const float4*)&sB1[tx * 8 + 4];

    float rp[8];
#pragma unroll
    for (int i = 0; i < 8; i++) {
        float s = 0.f;
#pragma unroll
        for (int j = 0; j < 8; j++) {
            float v = acc[i][j] + b1f[j];
            v = fmaxf(v, 0.f);
            s = fmaf(v, w2f[j], s);
        }
        rp[i] = s;
    }
    // partners share ty (same 16-lane half of the warp): xor over low 4 lane bits
#pragma unroll
    for (int off = 8; off > 0; off >>= 1)
#pragma unroll
        for (int i = 0; i < 8; i++)
            rp[i] += __shfl_xor_sync(0xffffffffu, rp[i], off);

    if (tx == 0) {
#pragma unroll
        for (int i = 0; i < 8; i++)
            atomicAdd(&g_rowsum[e * C_CAP + row0 + ty * 8 + i], rp[i]);
    }
}

// ---------------- K5: combine ----------------
__global__ void k_combine() {
    int t = blockIdx.x * blockDim.x + threadIdx.x;
    if (t >= T_TOK) return;
    float y = 0.f;
    int p0 = g_p0[t];
    if (p0 >= 0) {
        int e = g_e0[t];
        y += g_g0[t] * (g_rowsum[e * C_CAP + p0] + g_b2sum[e]);
    }
    int p1 = g_p1[t];
    if (p1 >= 0) {
        int e = g_e1[t];
        y += g_g1[t] * (g_rowsum[e * C_CAP + p1] + g_b2sum[e]);
    }
    g_y[t] = y;
}

// ---------------- K6: log_softmax over S per batch ----------------
__global__ void k_lsm(float* __restrict__ out) {
    __shared__ float red[256];
    int b = blockIdx.x, tid = threadIdx.x;
    const float* yr = g_y + (size_t)b * S_SEQ;

    float m = -INFINITY;
    for (int s = tid; s < S_SEQ; s += 256) m = fmaxf(m, yr[s]);
    red[tid] = m; __syncthreads();
    for (int off = 128; off > 0; off >>= 1) {
        if (tid < off) red[tid] = fmaxf(red[tid], red[tid + off]);
        __syncthreads();
    }
    m = red[0]; __syncthreads();

    float sum = 0.f;
    for (int s = tid; s < S_SEQ; s += 256) sum += expf(yr[s] - m);
    red[tid] = sum; __syncthreads();
    for (int off = 128; off > 0; off >>= 1) {
        if (tid < off) red[tid] += red[tid + off];
        __syncthreads();
    }
    float lse = m + logf(red[0]);

    for (int s = tid; s < S_SEQ; s += 256)
        out[(size_t)b * S_SEQ + s] = yr[s] - lse;
}

// ---------------- launch ----------------
extern "C" void kernel_launch(void* const* d_in, const int* in_sizes, int n_in,
                              void* d_out, int out_size) {
    const float* x  = (const float*)d_in[0];
    const float* Wg = (const float*)d_in[1];
    const float* W1 = (const float*)d_in[2];
    const float* b1 = (const float*)d_in[3];
    const float* W2 = (const float*)d_in[4];
    const float* b2 = (const float*)d_in[5];
    float* out = (float*)d_out;

    k_init<<<(E_EXP * C_CAP + 255) / 256, 256>>>();
    k_gate<<<T_TOK / 8, 256>>>(x, Wg);
    k_scan<<<1, SCAN_T>>>();
    k_w2sum<<<(E_EXP * H_DIM) / 8, 256>>>(W2);
    k_b2sum<<<1, 256>>>(b2);
    k_ffn<<<dim3(H_DIM / BN, C_CAP / BM, E_EXP), 256>>>(x, W1, b1);
    k_combine<<<T_TOK / 256, 256>>>();
    k_lsm<<<B_BATCH, 256>>>(out);
}